// round 1
// baseline (speedup 1.0000x reference)
#include <cuda_runtime.h>
#include <cuda_bf16.h>

#define Bsz 4
#define Nn  2048
#define Ff  256
#define Hh  8
#define Oo  256

// Scratch (allocation-free rule: __device__ globals)
__device__ float g_xw[(size_t)Bsz * Hh * Nn * Ff];   //  64 MB: [B,H,N,F]
__device__ float g_sc[(size_t)Bsz * Hh * Nn * Nn];   // 512 MB: [B,H,N,N]
__device__ float g_ms[(size_t)Bsz * Nn * Hh * Ff];   //  64 MB: [B,N,H,F] (concat layout)

// ---------------------------------------------------------------------------
// Generic batched GEMM: C = alpha * A * op(B) (+ bias), 64x64x16 tiles,
// 256 threads, 4x4 microtile per thread. All dims assumed multiples of tile.
// Batch index z decomposed as z1 = z / Z2, z2 = z % Z2 with independent strides
// (lets one kernel address [B,H,...] tensors and the [B,N,H,F] concat output).
// ---------------------------------------------------------------------------
template <bool TRANSB, bool BIAS>
__global__ __launch_bounds__(256) void gemm64(
    const float* __restrict__ A, const float* __restrict__ B,
    float* __restrict__ C, const float* __restrict__ bias,
    int M, int N, int K, int lda, int ldb, int ldc,
    long long sA1, long long sA2,
    long long sB1, long long sB2,
    long long sC1, long long sC2,
    int Z2, float alpha)
{
    __shared__ float As[16][64];   // [k][m]
    __shared__ float Bs[16][64];   // [k][n]

    const int z  = blockIdx.z;
    const int z1 = z / Z2, z2 = z % Z2;
    A += (size_t)z1 * sA1 + (size_t)z2 * sA2;
    B += (size_t)z1 * sB1 + (size_t)z2 * sB2;
    C += (size_t)z1 * sC1 + (size_t)z2 * sC2;

    const int n0 = blockIdx.x * 64;
    const int m0 = blockIdx.y * 64;

    const int tid = threadIdx.x;
    const int tx = tid & 15, ty = tid >> 4;     // compute mapping (16x16)
    const int lr = tid >> 2, lv = tid & 3;      // transpose-load mapping (64x4)

    float acc[4][4] = {};

    for (int k0 = 0; k0 < K; k0 += 16) {
        // Global loads into registers (A always row-major [M,K], transpose to smem)
        float4 av = *reinterpret_cast<const float4*>(
            &A[(size_t)(m0 + lr) * lda + k0 + lv * 4]);
        float4 bv;
        if (TRANSB) {
            // B is [N,K]: Bs[kk][n] = B[n0+n][k0+kk]
            bv = *reinterpret_cast<const float4*>(
                &B[(size_t)(n0 + lr) * ldb + k0 + lv * 4]);
        } else {
            // B is [K,N]: Bs[kk][n] direct
            bv = *reinterpret_cast<const float4*>(
                &B[(size_t)(k0 + ty) * ldb + n0 + tx * 4]);
        }

        __syncthreads();   // protect previous iteration's smem reads

        As[lv * 4 + 0][lr] = av.x;
        As[lv * 4 + 1][lr] = av.y;
        As[lv * 4 + 2][lr] = av.z;
        As[lv * 4 + 3][lr] = av.w;
        if (TRANSB) {
            Bs[lv * 4 + 0][lr] = bv.x;
            Bs[lv * 4 + 1][lr] = bv.y;
            Bs[lv * 4 + 2][lr] = bv.z;
            Bs[lv * 4 + 3][lr] = bv.w;
        } else {
            *reinterpret_cast<float4*>(&Bs[ty][tx * 4]) = bv;
        }
        __syncthreads();

#pragma unroll
        for (int kk = 0; kk < 16; kk++) {
            float4 a = *reinterpret_cast<float4*>(&As[kk][ty * 4]);
            float4 b = *reinterpret_cast<float4*>(&Bs[kk][tx * 4]);
            float ar[4] = {a.x, a.y, a.z, a.w};
            float br[4] = {b.x, b.y, b.z, b.w};
#pragma unroll
            for (int i = 0; i < 4; i++)
#pragma unroll
                for (int j = 0; j < 4; j++)
                    acc[i][j] += ar[i] * br[j];
        }
    }

#pragma unroll
    for (int i = 0; i < 4; i++) {
        float4 o;
        o.x = acc[i][0] * alpha;
        o.y = acc[i][1] * alpha;
        o.z = acc[i][2] * alpha;
        o.w = acc[i][3] * alpha;
        if (BIAS) {
            o.x += bias[n0 + tx * 4 + 0];
            o.y += bias[n0 + tx * 4 + 1];
            o.z += bias[n0 + tx * 4 + 2];
            o.w += bias[n0 + tx * 4 + 3];
        }
        *reinterpret_cast<float4*>(
            &C[(size_t)(m0 + ty * 4 + i) * ldc + n0 + tx * 4]) = o;
    }
}

// ---------------------------------------------------------------------------
// Row softmax over rows of length 2048 (in place). One block (256 thr) per row.
// ---------------------------------------------------------------------------
__global__ __launch_bounds__(256) void softmax2048(float* __restrict__ s)
{
    const size_t base = (size_t)blockIdx.x * 2048;
    const int tid = threadIdx.x;
    __shared__ float red[256];

    float v[8];
    float m = -1e30f;
#pragma unroll
    for (int i = 0; i < 8; i++) {
        v[i] = s[base + tid + i * 256];
        m = fmaxf(m, v[i]);
    }
    red[tid] = m;
    __syncthreads();
#pragma unroll
    for (int off = 128; off > 0; off >>= 1) {
        if (tid < off) red[tid] = fmaxf(red[tid], red[tid + off]);
        __syncthreads();
    }
    m = red[0];
    __syncthreads();

    float sum = 0.f;
#pragma unroll
    for (int i = 0; i < 8; i++) {
        v[i] = expf(v[i] - m);
        sum += v[i];
    }
    red[tid] = sum;
    __syncthreads();
#pragma unroll
    for (int off = 128; off > 0; off >>= 1) {
        if (tid < off) red[tid] += red[tid + off];
        __syncthreads();
    }
    const float inv = 1.0f / red[0];
#pragma unroll
    for (int i = 0; i < 8; i++)
        s[base + tid + i * 256] = v[i] * inv;
}

// ---------------------------------------------------------------------------
extern "C" void kernel_launch(void* const* d_in, const int* in_sizes, int n_in,
                              void* d_out, int out_size)
{
    const float* nodes = (const float*)d_in[0];   // [B,N,F]
    const float* Wh    = (const float*)d_in[1];   // [H,F,F]
    const float* Wo    = (const float*)d_in[2];   // [H*F,O]
    const float* bias  = (const float*)d_in[3];   // [O]
    float* out = (float*)d_out;                   // [B,N,O]

    float *xw, *sc, *ms;
    cudaGetSymbolAddress((void**)&xw, g_xw);
    cudaGetSymbolAddress((void**)&sc, g_sc);
    cudaGetSymbolAddress((void**)&ms, g_ms);

    const float norm = 0.0625f;   // 1/sqrt(256)
    dim3 blk(256);

    // 1) xw[b,h] = nodes[b] @ W_heads[h]            (NN, M=N, N=F, K=F)
    gemm64<false, false><<<dim3(Ff / 64, Nn / 64, Bsz * Hh), blk>>>(
        nodes, Wh, xw, nullptr,
        Nn, Ff, Ff, Ff, Ff, Ff,
        (long long)Nn * Ff, 0,
        0, (long long)Ff * Ff,
        (long long)Hh * Nn * Ff, (long long)Nn * Ff,
        Hh, 1.0f);

    // 2) scores[b,h] = norm * xw[b,h] @ nodes[b]^T  (NT, M=N, N=N, K=F)
    gemm64<true, false><<<dim3(Nn / 64, Nn / 64, Bsz * Hh), blk>>>(
        xw, nodes, sc, nullptr,
        Nn, Nn, Ff, Ff, Ff, Nn,
        (long long)Hh * Nn * Ff, (long long)Nn * Ff,
        (long long)Nn * Ff, 0,
        (long long)Hh * Nn * Nn, (long long)Nn * Nn,
        Hh, norm);

    // 3) softmax over last axis
    softmax2048<<<Bsz * Hh * Nn, 256>>>(sc);

    // 4) msgs[b,:,h,:] = att[b,h] @ nodes[b]        (NN, M=N, N=F, K=N)
    //    written directly into concat layout [B,N,H*F] via ldc=H*F, col base h*F
    gemm64<false, false><<<dim3(Ff / 64, Nn / 64, Bsz * Hh), blk>>>(
        sc, nodes, ms, nullptr,
        Nn, Ff, Nn, Nn, Ff, Hh * Ff,
        (long long)Hh * Nn * Nn, (long long)Nn * Nn,
        (long long)Nn * Ff, 0,
        (long long)Nn * Hh * Ff, (long long)Ff,
        Hh, 1.0f);

    // 5) out[b] = msgs[b] @ W_out + bias            (NN, M=N, N=O, K=H*F)
    gemm64<false, true><<<dim3(Oo / 64, Nn / 64, Bsz), blk>>>(
        ms, Wo, out, bias,
        Nn, Oo, Hh * Ff, Hh * Ff, Oo, Oo,
        (long long)Nn * Hh * Ff, 0,
        0, 0,
        (long long)Nn * Oo, 0,
        1, 1.0f);
}

// round 4
// speedup vs baseline: 1.3835x; 1.3835x over previous
#include <cuda_runtime.h>
#include <cuda_bf16.h>
#include <cstdint>

#define Bsz 4
#define Nn  2048
#define Ff  256
#define Hh  8
#define Oo  256

// ------------------------- device scratch (no allocs) -----------------------
__device__ __align__(256) __nv_bfloat16 g_nodes_h[(size_t)Bsz*Nn*Ff];
__device__ __align__(256) __nv_bfloat16 g_nodes_l[(size_t)Bsz*Nn*Ff];
__device__ __align__(256) __nv_bfloat16 g_nodesT_h[(size_t)Bsz*Ff*Nn];
__device__ __align__(256) __nv_bfloat16 g_nodesT_l[(size_t)Bsz*Ff*Nn];
__device__ __align__(256) __nv_bfloat16 g_WhT_h[(size_t)Hh*Ff*Ff];
__device__ __align__(256) __nv_bfloat16 g_WhT_l[(size_t)Hh*Ff*Ff];
__device__ __align__(256) __nv_bfloat16 g_WoT_h[(size_t)Oo*Hh*Ff];
__device__ __align__(256) __nv_bfloat16 g_WoT_l[(size_t)Oo*Hh*Ff];
__device__ __align__(256) __nv_bfloat16 g_xw_h[(size_t)Bsz*Hh*Nn*Ff];
__device__ __align__(256) __nv_bfloat16 g_xw_l[(size_t)Bsz*Hh*Nn*Ff];
__device__ __align__(256) float         g_sc  [(size_t)Bsz*Hh*Nn*Nn];
__device__ __align__(256) __nv_bfloat16 g_att_h[(size_t)Bsz*Hh*Nn*Nn];
__device__ __align__(256) __nv_bfloat16 g_att_l[(size_t)Bsz*Hh*Nn*Nn];
__device__ __align__(256) __nv_bfloat16 g_ms_h[(size_t)Bsz*Nn*Hh*Ff];
__device__ __align__(256) __nv_bfloat16 g_ms_l[(size_t)Bsz*Nn*Hh*Ff];

// ------------------------------ PTX helpers ---------------------------------
__device__ __forceinline__ uint32_t smem_u32(const void* p) {
    uint32_t a;
    asm("{ .reg .u64 t; cvta.to.shared.u64 t, %1; cvt.u32.u64 %0, t; }" : "=r"(a) : "l"(p));
    return a;
}
#define CP_ASYNC16(dst, src) \
    asm volatile("cp.async.cg.shared.global [%0], [%1], 16;" :: "r"(dst), "l"(src))
#define CP_COMMIT() asm volatile("cp.async.commit_group;" ::: "memory")
#define CP_WAIT2()  asm volatile("cp.async.wait_group 2;" ::: "memory")

__device__ __forceinline__ void ldsm_x4(uint32_t& r0, uint32_t& r1, uint32_t& r2,
                                        uint32_t& r3, uint32_t addr) {
    asm volatile("ldmatrix.sync.aligned.m8n8.x4.shared.b16 {%0,%1,%2,%3}, [%4];"
                 : "=r"(r0), "=r"(r1), "=r"(r2), "=r"(r3) : "r"(addr));
}
__device__ __forceinline__ void ldsm_x2(uint32_t& r0, uint32_t& r1, uint32_t addr) {
    asm volatile("ldmatrix.sync.aligned.m8n8.x2.shared.b16 {%0,%1}, [%2];"
                 : "=r"(r0), "=r"(r1) : "r"(addr));
}
__device__ __forceinline__ void mma_bf16(float* d, const uint32_t* a, const uint32_t* b) {
    asm volatile(
        "mma.sync.aligned.m16n8k16.row.col.f32.bf16.bf16.f32 "
        "{%0,%1,%2,%3}, {%4,%5,%6,%7}, {%8,%9}, {%0,%1,%2,%3};"
        : "+f"(d[0]), "+f"(d[1]), "+f"(d[2]), "+f"(d[3])
        : "r"(a[0]), "r"(a[1]), "r"(a[2]), "r"(a[3]), "r"(b[0]), "r"(b[1]));
}

// --------------------------- smem layout constants ---------------------------
// Tile: A 128 rows x 32 bf16, B 128 rows x 32 bf16; row pitch 80B (40 bf16):
// 80/16 = 5, gcd(5,8)=1 -> ldmatrix 8-row reads hit 8 distinct 16B phases.
#define ROWB      80
#define A_OFF     0
#define B_OFF     (128 * ROWB)       // 10240
#define STAGE_SZ  (256 * ROWB)       // 20480
#define NSTAGE    4
#define SMEM_SZ   (NSTAGE * STAGE_SZ) // 81920

// ----------------------------- tile load (cp.async) --------------------------
__device__ __forceinline__ void load_chunk(
    uint32_t sb,
    const __nv_bfloat16* __restrict__ A, const __nv_bfloat16* __restrict__ B,
    int m0, int n0, int k0, int lda, int ldb, int tid)
{
#pragma unroll
    for (int q = 0; q < 2; q++) {               // A: 128 rows x 4 x 16B
        int u = q * 256 + tid;
        int r = u >> 2, c = u & 3;
        const char* src = (const char*)(A + (size_t)(m0 + r) * lda + k0 + c * 8);
        CP_ASYNC16(sb + A_OFF + r * ROWB + c * 16, src);
    }
#pragma unroll
    for (int q = 0; q < 2; q++) {               // B: 128 rows x 4 x 16B
        int u = q * 256 + tid;
        int r = u >> 2, c = u & 3;
        const char* src = (const char*)(B + (size_t)(n0 + r) * ldb + k0 + c * 8);
        CP_ASYNC16(sb + B_OFF + r * ROWB + c * 16, src);
    }
    CP_COMMIT();
}

// --------------------------------- GEMM --------------------------------------
// C[M,N] = alpha * A @ B^T, fp32 emulation via 3 split-bf16 passes (AhBh+AlBh+AhBl).
// CTA tile 128x128, 8 warps (2 M x 4 N), warp tile 64x32, mma.sync m16n8k16.
// OUTMODE: 0=f32, 1=f32+bias, 2=split hi/lo bf16.
template <int OUTMODE>
__global__ __launch_bounds__(256, 1) void tc_gemm(
    const __nv_bfloat16* __restrict__ Ah, const __nv_bfloat16* __restrict__ Al,
    const __nv_bfloat16* __restrict__ Bh, const __nv_bfloat16* __restrict__ Bl,
    float* __restrict__ C, __nv_bfloat16* __restrict__ Ch, __nv_bfloat16* __restrict__ Cl,
    const float* __restrict__ bias,
    int K, int lda, int ldb, int ldc,
    long long sA1, long long sA2, long long sB1, long long sB2,
    long long sC1, long long sC2, int Z2, float alpha)
{
    extern __shared__ char smem[];
    const uint32_t sbase = smem_u32(smem);
    const int tid = threadIdx.x, wid = tid >> 5, lane = tid & 31;
    const int warp_m = wid & 1, warp_n = wid >> 1;

    const int z = blockIdx.z, z1 = z / Z2, z2 = z % Z2;
    Ah += (size_t)z1 * sA1 + (size_t)z2 * sA2;
    Al += (size_t)z1 * sA1 + (size_t)z2 * sA2;
    Bh += (size_t)z1 * sB1 + (size_t)z2 * sB2;
    Bl += (size_t)z1 * sB1 + (size_t)z2 * sB2;
    const size_t coff = (size_t)z1 * sC1 + (size_t)z2 * sC2;

    const int n0 = blockIdx.x * 128;
    const int m0 = blockIdx.y * 128;

    const int nk  = K >> 5;              // 32-wide chunks per pass
    const int nch = 3 * nk;              // 3 split passes

    float acc[16][4];
#pragma unroll
    for (int i = 0; i < 16; i++)
#pragma unroll
        for (int j = 0; j < 4; j++) acc[i][j] = 0.f;

    // ldmatrix base addresses for this lane (within a stage)
    // A x4: row = lane&15, col-half = lane>>4 (8 bf16 = 16B)
    const uint32_t a_lane = (uint32_t)((lane & 15) * ROWB + (lane >> 4) * 16);
    // B x2: lanes0-7 row n+lane @k; lanes8-15 row n+lane-8 @k+8 (lanes>=16 mirror)
    const uint32_t b_lane = (uint32_t)((lane & 7) * ROWB + ((lane >> 3) & 1) * 16);

    // prologue
#pragma unroll
    for (int c = 0; c < NSTAGE - 1; c++) {
        int p = c / nk, kc = c - p * nk;
        const __nv_bfloat16* Ap = (p == 1) ? Al : Ah;
        const __nv_bfloat16* Bp = (p == 2) ? Bl : Bh;
        load_chunk(sbase + (c & (NSTAGE - 1)) * STAGE_SZ, Ap, Bp,
                   m0, n0, kc << 5, lda, ldb, tid);
    }

    for (int c = 0; c < nch; c++) {
        CP_WAIT2();
        __syncthreads();

        const uint32_t sb = sbase + (c & (NSTAGE - 1)) * STAGE_SZ;
        const uint32_t abase = sb + A_OFF + (uint32_t)(warp_m * 64 * ROWB) + a_lane;
        const uint32_t bbase = sb + B_OFF + (uint32_t)(warp_n * 32 * ROWB) + b_lane;

#pragma unroll
        for (int ks = 0; ks < 2; ks++) {        // two k16 steps per 32-chunk
            uint32_t af[4][4], bf[4][2];
#pragma unroll
            for (int mi = 0; mi < 4; mi++)
                ldsm_x4(af[mi][0], af[mi][1], af[mi][2], af[mi][3],
                        abase + mi * 16 * ROWB + ks * 32);
#pragma unroll
            for (int ni = 0; ni < 4; ni++)
                ldsm_x2(bf[ni][0], bf[ni][1],
                        bbase + ni * 8 * ROWB + ks * 32);
#pragma unroll
            for (int mi = 0; mi < 4; mi++)
#pragma unroll
                for (int ni = 0; ni < 4; ni++)
                    mma_bf16(acc[mi * 4 + ni], af[mi], bf[ni]);
        }

        if (c + NSTAGE - 1 < nch) {
            int cn = c + NSTAGE - 1;
            int p = cn / nk, kc = cn - p * nk;
            const __nv_bfloat16* Ap = (p == 1) ? Al : Ah;
            const __nv_bfloat16* Bp = (p == 2) ? Bl : Bh;
            load_chunk(sbase + (cn & (NSTAGE - 1)) * STAGE_SZ, Ap, Bp,
                       m0, n0, kc << 5, lda, ldb, tid);
        } else {
            CP_COMMIT();          // keep wait_group accounting exact at tail
        }
    }

    // ---------------- epilogue: registers -> GMEM ----------------------------
    const int r0 = m0 + warp_m * 64 + (lane >> 2);
    const int c0 = n0 + warp_n * 32 + (lane & 3) * 2;
#pragma unroll
    for (int mi = 0; mi < 4; mi++) {
#pragma unroll
        for (int ni = 0; ni < 4; ni++) {
            float* d = acc[mi * 4 + ni];
            const int gr = r0 + mi * 16;
            const int gc = c0 + ni * 8;
#pragma unroll
            for (int h = 0; h < 2; h++) {       // rows gr, gr+8
                float vx = d[h * 2 + 0] * alpha;
                float vy = d[h * 2 + 1] * alpha;
                const size_t off = coff + (size_t)(gr + h * 8) * ldc + gc;
                if (OUTMODE == 2) {
                    __nv_bfloat162 hv = __floats2bfloat162_rn(vx, vy);
                    float rx = vx - __low2float(hv);
                    float ry = vy - __high2float(hv);
                    __nv_bfloat162 lv = __floats2bfloat162_rn(rx, ry);
                    *reinterpret_cast<__nv_bfloat162*>(Ch + off) = hv;
                    *reinterpret_cast<__nv_bfloat162*>(Cl + off) = lv;
                } else {
                    if (OUTMODE == 1) { vx += bias[gc]; vy += bias[gc + 1]; }
                    float2 o; o.x = vx; o.y = vy;
                    *reinterpret_cast<float2*>(C + off) = o;
                }
            }
        }
    }
}

// ------------------------------ helper kernels --------------------------------
__global__ __launch_bounds__(256) void split_plain(
    const float* __restrict__ in, __nv_bfloat16* __restrict__ oh,
    __nv_bfloat16* __restrict__ ol, int n)
{
    int i = blockIdx.x * 256 + threadIdx.x;
    if (i < n) {
        float v = in[i];
        __nv_bfloat16 h = __float2bfloat16(v);
        oh[i] = h;
        ol[i] = __float2bfloat16(v - __bfloat162float(h));
    }
}

// in: [Z][R][C] fp32  ->  out hi/lo: [Z][C][R] bf16
__global__ __launch_bounds__(256) void split_trans(
    const float* __restrict__ in, __nv_bfloat16* __restrict__ oh,
    __nv_bfloat16* __restrict__ ol, int R, int C)
{
    const size_t base = (size_t)blockIdx.y * (size_t)R * C;
    int i = blockIdx.x * 256 + threadIdx.x;
    if (i < R * C) {
        int r = i / C, c = i - r * C;
        float v = in[base + i];
        size_t o = base + (size_t)c * R + r;
        __nv_bfloat16 h = __float2bfloat16(v);
        oh[o] = h;
        ol[o] = __float2bfloat16(v - __bfloat162float(h));
    }
}

// softmax over rows of 2048 fp32, emits att hi/lo bf16
__global__ __launch_bounds__(256) void softmax2048s(
    const float* __restrict__ s, __nv_bfloat16* __restrict__ ah,
    __nv_bfloat16* __restrict__ al)
{
    const size_t base = (size_t)blockIdx.x * 2048;
    const int tid = threadIdx.x;
    __shared__ float red[256];

    float v[8];
    float m = -1e30f;
#pragma unroll
    for (int i = 0; i < 8; i++) {
        v[i] = s[base + tid + i * 256];
        m = fmaxf(m, v[i]);
    }
    red[tid] = m;
    __syncthreads();
#pragma unroll
    for (int off = 128; off > 0; off >>= 1) {
        if (tid < off) red[tid] = fmaxf(red[tid], red[tid + off]);
        __syncthreads();
    }
    m = red[0];
    __syncthreads();

    float sum = 0.f;
#pragma unroll
    for (int i = 0; i < 8; i++) {
        v[i] = __expf(v[i] - m);
        sum += v[i];
    }
    red[tid] = sum;
    __syncthreads();
#pragma unroll
    for (int off = 128; off > 0; off >>= 1) {
        if (tid < off) red[tid] += red[tid + off];
        __syncthreads();
    }
    const float inv = 1.0f / red[0];
#pragma unroll
    for (int i = 0; i < 8; i++) {
        float p = v[i] * inv;
        __nv_bfloat16 h = __float2bfloat16(p);
        ah[base + tid + i * 256] = h;
        al[base + tid + i * 256] = __float2bfloat16(p - __bfloat162float(h));
    }
}

// ---------------------------------- launch ------------------------------------
extern "C" void kernel_launch(void* const* d_in, const int* in_sizes, int n_in,
                              void* d_out, int out_size)
{
    const float* nodes = (const float*)d_in[0];   // [B,N,F]
    const float* Wh    = (const float*)d_in[1];   // [H,F,F]
    const float* Wo    = (const float*)d_in[2];   // [H*F,O]
    const float* bias  = (const float*)d_in[3];   // [O]
    float* out = (float*)d_out;                   // [B,N,O]

    __nv_bfloat16 *nodes_h, *nodes_l, *nodesT_h, *nodesT_l, *WhT_h, *WhT_l;
    __nv_bfloat16 *WoT_h, *WoT_l, *xw_h, *xw_l, *att_h, *att_l, *ms_h, *ms_l;
    float* sc;
    cudaGetSymbolAddress((void**)&nodes_h,  g_nodes_h);
    cudaGetSymbolAddress((void**)&nodes_l,  g_nodes_l);
    cudaGetSymbolAddress((void**)&nodesT_h, g_nodesT_h);
    cudaGetSymbolAddress((void**)&nodesT_l, g_nodesT_l);
    cudaGetSymbolAddress((void**)&WhT_h,    g_WhT_h);
    cudaGetSymbolAddress((void**)&WhT_l,    g_WhT_l);
    cudaGetSymbolAddress((void**)&WoT_h,    g_WoT_h);
    cudaGetSymbolAddress((void**)&WoT_l,    g_WoT_l);
    cudaGetSymbolAddress((void**)&xw_h,     g_xw_h);
    cudaGetSymbolAddress((void**)&xw_l,     g_xw_l);
    cudaGetSymbolAddress((void**)&sc,       g_sc);
    cudaGetSymbolAddress((void**)&att_h,    g_att_h);
    cudaGetSymbolAddress((void**)&att_l,    g_att_l);
    cudaGetSymbolAddress((void**)&ms_h,     g_ms_h);
    cudaGetSymbolAddress((void**)&ms_l,     g_ms_l);

    cudaFuncSetAttribute(tc_gemm<0>, cudaFuncAttributeMaxDynamicSharedMemorySize, SMEM_SZ);
    cudaFuncSetAttribute(tc_gemm<1>, cudaFuncAttributeMaxDynamicSharedMemorySize, SMEM_SZ);
    cudaFuncSetAttribute(tc_gemm<2>, cudaFuncAttributeMaxDynamicSharedMemorySize, SMEM_SZ);

    // ---- operand conversions -------------------------------------------------
    split_plain<<<(Bsz*Nn*Ff + 255) / 256, 256>>>(nodes, nodes_h, nodes_l, Bsz*Nn*Ff);
    split_trans<<<dim3((Nn*Ff + 255) / 256, Bsz), 256>>>(nodes, nodesT_h, nodesT_l, Nn, Ff);
    split_trans<<<dim3((Ff*Ff + 255) / 256, Hh), 256>>>(Wh, WhT_h, WhT_l, Ff, Ff);
    split_trans<<<dim3((Hh*Ff*Oo + 255) / 256, 1), 256>>>(Wo, WoT_h, WoT_l, Hh*Ff, Oo);

    const float norm = 0.0625f;   // 1/sqrt(256), folded into xw

    // 1) xw = norm * nodes @ Wh^T(pre-transposed)   (split output)
    tc_gemm<2><<<dim3(Ff/128, Nn/128, Bsz*Hh), 256, SMEM_SZ>>>(
        nodes_h, nodes_l, WhT_h, WhT_l,
        nullptr, xw_h, xw_l, nullptr,
        Ff, Ff, Ff, Ff,
        (long long)Nn*Ff, 0,
        0, (long long)Ff*Ff,
        (long long)Hh*Nn*Ff, (long long)Nn*Ff,
        Hh, norm);

    // 2) scores = xw @ nodes^T   (fp32 output)
    tc_gemm<0><<<dim3(Nn/128, Nn/128, Bsz*Hh), 256, SMEM_SZ>>>(
        xw_h, xw_l, nodes_h, nodes_l,
        sc, nullptr, nullptr, nullptr,
        Ff, Ff, Ff, Nn,
        (long long)Hh*Nn*Ff, (long long)Nn*Ff,
        (long long)Nn*Ff, 0,
        (long long)Hh*Nn*Nn, (long long)Nn*Nn,
        Hh, 1.0f);

    // 3) softmax -> att hi/lo
    softmax2048s<<<Bsz*Hh*Nn, 256>>>(sc, att_h, att_l);

    // 4) msgs = att @ nodes  (split output, concat layout [B,N,H*F])
    tc_gemm<2><<<dim3(Ff/128, Nn/128, Bsz*Hh), 256, SMEM_SZ>>>(
        att_h, att_l, nodesT_h, nodesT_l,
        nullptr, ms_h, ms_l, nullptr,
        Nn, Nn, Nn, Hh*Ff,
        (long long)Hh*Nn*Nn, (long long)Nn*Nn,
        (long long)Ff*Nn, 0,
        (long long)Nn*Hh*Ff, (long long)Ff,
        Hh, 1.0f);

    // 5) out = msgs @ Wout + bias
    tc_gemm<1><<<dim3(Oo/128, Nn/128, Bsz), 256, SMEM_SZ>>>(
        ms_h, ms_l, WoT_h, WoT_l,
        out, nullptr, nullptr, bias,
        Hh*Ff, Hh*Ff, Hh*Ff, Oo,
        (long long)Nn*Hh*Ff, 0,
        0, 0,
        (long long)Nn*Oo, 0,
        1, 1.0f);
}

// round 5
// speedup vs baseline: 2.3631x; 1.7081x over previous
#include <cuda_runtime.h>
#include <cuda_bf16.h>
#include <cstdint>

#define Bsz 4
#define Nn  2048
#define Ff  256
#define Hh  8
#define Oo  256

// ------------------------- device scratch (no allocs) -----------------------
__device__ __align__(256) __nv_bfloat16 g_nodes_h[(size_t)Bsz*Nn*Ff];
__device__ __align__(256) __nv_bfloat16 g_nodes_l[(size_t)Bsz*Nn*Ff];
__device__ __align__(256) __nv_bfloat16 g_nodesT_h[(size_t)Bsz*Ff*Nn];
__device__ __align__(256) __nv_bfloat16 g_nodesT_l[(size_t)Bsz*Ff*Nn];
__device__ __align__(256) __nv_bfloat16 g_WhT_h[(size_t)Hh*Ff*Ff];
__device__ __align__(256) __nv_bfloat16 g_WhT_l[(size_t)Hh*Ff*Ff];
__device__ __align__(256) __nv_bfloat16 g_WoT_h[(size_t)Oo*Hh*Ff];
__device__ __align__(256) __nv_bfloat16 g_WoT_l[(size_t)Oo*Hh*Ff];
__device__ __align__(256) __nv_bfloat16 g_xw_h[(size_t)Bsz*Hh*Nn*Ff];
__device__ __align__(256) __nv_bfloat16 g_xw_l[(size_t)Bsz*Hh*Nn*Ff];
__device__ __align__(256) float         g_sc  [(size_t)Bsz*Hh*Nn*Nn];
__device__ __align__(256) __nv_bfloat16 g_att_h[(size_t)Bsz*Hh*Nn*Nn];
__device__ __align__(256) __nv_bfloat16 g_att_l[(size_t)Bsz*Hh*Nn*Nn];
__device__ __align__(256) __nv_bfloat16 g_ms_h[(size_t)Bsz*Nn*Hh*Ff];
__device__ __align__(256) __nv_bfloat16 g_ms_l[(size_t)Bsz*Nn*Hh*Ff];

// ------------------------------ PTX helpers ---------------------------------
__device__ __forceinline__ uint32_t smem_u32(const void* p) {
    uint32_t a;
    asm("{ .reg .u64 t; cvta.to.shared.u64 t, %1; cvt.u32.u64 %0, t; }" : "=r"(a) : "l"(p));
    return a;
}
#define CP_ASYNC16(dst, src) \
    asm volatile("cp.async.cg.shared.global [%0], [%1], 16;" :: "r"(dst), "l"(src))
#define CP_COMMIT() asm volatile("cp.async.commit_group;" ::: "memory")
#define CP_WAIT2()  asm volatile("cp.async.wait_group 2;" ::: "memory")

__device__ __forceinline__ void ldsm_x4(uint32_t& r0, uint32_t& r1, uint32_t& r2,
                                        uint32_t& r3, uint32_t addr) {
    asm volatile("ldmatrix.sync.aligned.m8n8.x4.shared.b16 {%0,%1,%2,%3}, [%4];"
                 : "=r"(r0), "=r"(r1), "=r"(r2), "=r"(r3) : "r"(addr));
}
__device__ __forceinline__ void ldsm_x2(uint32_t& r0, uint32_t& r1, uint32_t addr) {
    asm volatile("ldmatrix.sync.aligned.m8n8.x2.shared.b16 {%0,%1}, [%2];"
                 : "=r"(r0), "=r"(r1) : "r"(addr));
}
__device__ __forceinline__ void mma_bf16(float* d, const uint32_t* a, const uint32_t* b) {
    asm volatile(
        "mma.sync.aligned.m16n8k16.row.col.f32.bf16.bf16.f32 "
        "{%0,%1,%2,%3}, {%4,%5,%6,%7}, {%8,%9}, {%0,%1,%2,%3};"
        : "+f"(d[0]), "+f"(d[1]), "+f"(d[2]), "+f"(d[3])
        : "r"(a[0]), "r"(a[1]), "r"(a[2]), "r"(a[3]), "r"(b[0]), "r"(b[1]));
}

// --------------------------- smem layout constants ---------------------------
// Row pitch 80B (64B data + 16B pad): 80/16=5, gcd(5,8)=1 -> conflict-free
// ldmatrix 8-row phases.
#define ROWB      80
#define NSTAGE    4

// ----------------------------- tile load (cp.async) --------------------------
template <int TM>
__device__ __forceinline__ void load_chunk(
    uint32_t sb,
    const __nv_bfloat16* __restrict__ A, const __nv_bfloat16* __restrict__ B,
    int m0, int n0, int k0, int lda, int ldb, int tid)
{
    constexpr int THREADS = TM * 2;
#pragma unroll
    for (int q = 0; q < (TM * 4) / THREADS; q++) {      // A: TM rows x 4 x 16B
        int u = q * THREADS + tid;
        int r = u >> 2, c = u & 3;
        const char* src = (const char*)(A + (size_t)(m0 + r) * lda + k0 + c * 8);
        CP_ASYNC16(sb + r * ROWB + c * 16, src);
    }
#pragma unroll
    for (int q = 0; q < 512 / THREADS; q++) {           // B: 128 rows x 4 x 16B
        int u = q * THREADS + tid;
        int r = u >> 2, c = u & 3;
        const char* src = (const char*)(B + (size_t)(n0 + r) * ldb + k0 + c * 8);
        CP_ASYNC16(sb + TM * ROWB + r * ROWB + c * 16, src);
    }
    CP_COMMIT();
}

// --------------------------------- GEMM --------------------------------------
// C[M,N] = alpha * A @ B^T, fp32 emulation via 3 split-bf16 passes (AhBh+AlBh+AhBl).
// CTA tile TM x 128, TM*2 threads, warp tile 64x32 (warps (TM/64) x 4).
// OUTMODE: 0=f32, 1=f32+bias, 2=split hi/lo bf16.
template <int TM, int OUTMODE>
__global__ __launch_bounds__(TM * 2, 1) void tc_gemm(
    const __nv_bfloat16* __restrict__ Ah, const __nv_bfloat16* __restrict__ Al,
    const __nv_bfloat16* __restrict__ Bh, const __nv_bfloat16* __restrict__ Bl,
    float* __restrict__ C, __nv_bfloat16* __restrict__ Ch, __nv_bfloat16* __restrict__ Cl,
    const float* __restrict__ bias,
    int K, int lda, int ldb, int ldc,
    long long sA1, long long sA2, long long sB1, long long sB2,
    long long sC1, long long sC2, int Z2, float alpha)
{
    constexpr int WM = TM / 64;                  // warp rows
    constexpr int STAGE_SZ = (TM + 128) * ROWB;

    extern __shared__ char smem[];
    const uint32_t sbase = smem_u32(smem);
    const int tid = threadIdx.x, wid = tid >> 5, lane = tid & 31;
    const int warp_m = wid % WM, warp_n = wid / WM;

    const int z = blockIdx.z, z1 = z / Z2, z2 = z % Z2;
    Ah += (size_t)z1 * sA1 + (size_t)z2 * sA2;
    Al += (size_t)z1 * sA1 + (size_t)z2 * sA2;
    Bh += (size_t)z1 * sB1 + (size_t)z2 * sB2;
    Bl += (size_t)z1 * sB1 + (size_t)z2 * sB2;
    const size_t coff = (size_t)z1 * sC1 + (size_t)z2 * sC2;

    const int n0 = blockIdx.x * 128;
    const int m0 = blockIdx.y * TM;

    const int nk  = K >> 5;              // 32-wide chunks per pass
    const int nch = 3 * nk;              // 3 split passes

    float acc[16][4];
#pragma unroll
    for (int i = 0; i < 16; i++)
#pragma unroll
        for (int j = 0; j < 4; j++) acc[i][j] = 0.f;

    const uint32_t a_lane = (uint32_t)((lane & 15) * ROWB + (lane >> 4) * 16);
    const uint32_t b_lane = (uint32_t)((lane & 7) * ROWB + ((lane >> 3) & 1) * 16);

    // prologue
#pragma unroll
    for (int c = 0; c < NSTAGE - 1; c++) {
        int p = c / nk, kc = c - p * nk;
        const __nv_bfloat16* Ap = (p == 1) ? Al : Ah;
        const __nv_bfloat16* Bp = (p == 2) ? Bl : Bh;
        load_chunk<TM>(sbase + (c & (NSTAGE - 1)) * STAGE_SZ, Ap, Bp,
                       m0, n0, kc << 5, lda, ldb, tid);
    }

    for (int c = 0; c < nch; c++) {
        CP_WAIT2();
        __syncthreads();

        const uint32_t sb = sbase + (c & (NSTAGE - 1)) * STAGE_SZ;
        const uint32_t abase = sb + (uint32_t)(warp_m * 64 * ROWB) + a_lane;
        const uint32_t bbase = sb + (uint32_t)(TM * ROWB) +
                               (uint32_t)(warp_n * 32 * ROWB) + b_lane;

#pragma unroll
        for (int ks = 0; ks < 2; ks++) {        // two k16 steps per 32-chunk
            uint32_t af[4][4], bf[4][2];
#pragma unroll
            for (int mi = 0; mi < 4; mi++)
                ldsm_x4(af[mi][0], af[mi][1], af[mi][2], af[mi][3],
                        abase + mi * 16 * ROWB + ks * 32);
#pragma unroll
            for (int ni = 0; ni < 4; ni++)
                ldsm_x2(bf[ni][0], bf[ni][1],
                        bbase + ni * 8 * ROWB + ks * 32);
#pragma unroll
            for (int mi = 0; mi < 4; mi++)
#pragma unroll
                for (int ni = 0; ni < 4; ni++)
                    mma_bf16(acc[mi * 4 + ni], af[mi], bf[ni]);
        }

        if (c + NSTAGE - 1 < nch) {
            int cn = c + NSTAGE - 1;
            int p = cn / nk, kc = cn - p * nk;
            const __nv_bfloat16* Ap = (p == 1) ? Al : Ah;
            const __nv_bfloat16* Bp = (p == 2) ? Bl : Bh;
            load_chunk<TM>(sbase + (cn & (NSTAGE - 1)) * STAGE_SZ, Ap, Bp,
                           m0, n0, kc << 5, lda, ldb, tid);
        } else {
            CP_COMMIT();          // keep wait_group accounting exact at tail
        }
    }

    // ---------------- epilogue: registers -> GMEM ----------------------------
    const int r0 = m0 + warp_m * 64 + (lane >> 2);
    const int c0 = n0 + warp_n * 32 + (lane & 3) * 2;
#pragma unroll
    for (int mi = 0; mi < 4; mi++) {
#pragma unroll
        for (int ni = 0; ni < 4; ni++) {
            float* d = acc[mi * 4 + ni];
            const int gr = r0 + mi * 16;
            const int gc = c0 + ni * 8;
#pragma unroll
            for (int h = 0; h < 2; h++) {       // rows gr, gr+8
                float vx = d[h * 2 + 0] * alpha;
                float vy = d[h * 2 + 1] * alpha;
                const size_t off = coff + (size_t)(gr + h * 8) * ldc + gc;
                if (OUTMODE == 2) {
                    __nv_bfloat162 hv = __floats2bfloat162_rn(vx, vy);
                    float rx = vx - __low2float(hv);
                    float ry = vy - __high2float(hv);
                    __nv_bfloat162 lv = __floats2bfloat162_rn(rx, ry);
                    *reinterpret_cast<__nv_bfloat162*>(Ch + off) = hv;
                    *reinterpret_cast<__nv_bfloat162*>(Cl + off) = lv;
                } else {
                    if (OUTMODE == 1) { vx += bias[gc]; vy += bias[gc + 1]; }
                    float2 o; o.x = vx; o.y = vy;
                    *reinterpret_cast<float2*>(C + off) = o;
                }
            }
        }
    }
}

// ------------------------------ helper kernels --------------------------------
// nodes [B][N][F] -> row-major hi/lo AND transposed [B][F][N] hi/lo in one read
__global__ __launch_bounds__(256) void split_nodes(
    const float* __restrict__ in,
    __nv_bfloat16* __restrict__ oh, __nv_bfloat16* __restrict__ ol,
    __nv_bfloat16* __restrict__ th, __nv_bfloat16* __restrict__ tl)
{
    const size_t base = (size_t)blockIdx.y * (size_t)Nn * Ff;
    int i = blockIdx.x * 256 + threadIdx.x;
    int r = i >> 8, c = i & 255;            // F = 256
    float v = in[base + i];
    __nv_bfloat16 h = __float2bfloat16(v);
    __nv_bfloat16 l = __float2bfloat16(v - __bfloat162float(h));
    oh[base + i] = h;
    ol[base + i] = l;
    size_t o = base + (size_t)c * Nn + r;
    th[o] = h;
    tl[o] = l;
}

// in: [Z][R][C] fp32  ->  out hi/lo: [Z][C][R] bf16
__global__ __launch_bounds__(256) void split_trans(
    const float* __restrict__ in, __nv_bfloat16* __restrict__ oh,
    __nv_bfloat16* __restrict__ ol, int R, int C)
{
    const size_t base = (size_t)blockIdx.y * (size_t)R * C;
    int i = blockIdx.x * 256 + threadIdx.x;
    if (i < R * C) {
        int r = i / C, c = i - r * C;
        float v = in[base + i];
        size_t o = base + (size_t)c * R + r;
        __nv_bfloat16 h = __float2bfloat16(v);
        oh[o] = h;
        ol[o] = __float2bfloat16(v - __bfloat162float(h));
    }
}

// softmax over rows of 2048 fp32, emits att hi/lo bf16
__global__ __launch_bounds__(256) void softmax2048s(
    const float* __restrict__ s, __nv_bfloat16* __restrict__ ah,
    __nv_bfloat16* __restrict__ al)
{
    const size_t base = (size_t)blockIdx.x * 2048;
    const int tid = threadIdx.x;
    __shared__ float red[256];

    float v[8];
    float m = -1e30f;
#pragma unroll
    for (int i = 0; i < 8; i++) {
        v[i] = s[base + tid + i * 256];
        m = fmaxf(m, v[i]);
    }
    red[tid] = m;
    __syncthreads();
#pragma unroll
    for (int off = 128; off > 0; off >>= 1) {
        if (tid < off) red[tid] = fmaxf(red[tid], red[tid + off]);
        __syncthreads();
    }
    m = red[0];
    __syncthreads();

    float sum = 0.f;
#pragma unroll
    for (int i = 0; i < 8; i++) {
        v[i] = __expf(v[i] - m);
        sum += v[i];
    }
    red[tid] = sum;
    __syncthreads();
#pragma unroll
    for (int off = 128; off > 0; off >>= 1) {
        if (tid < off) red[tid] += red[tid + off];
        __syncthreads();
    }
    const float inv = 1.0f / red[0];
#pragma unroll
    for (int i = 0; i < 8; i++) {
        float p = v[i] * inv;
        __nv_bfloat16 h = __float2bfloat16(p);
        ah[base + tid + i * 256] = h;
        al[base + tid + i * 256] = __float2bfloat16(p - __bfloat162float(h));
    }
}

// ---------------------------------- launch ------------------------------------
extern "C" void kernel_launch(void* const* d_in, const int* in_sizes, int n_in,
                              void* d_out, int out_size)
{
    const float* nodes = (const float*)d_in[0];   // [B,N,F]
    const float* Wh    = (const float*)d_in[1];   // [H,F,F]
    const float* Wo    = (const float*)d_in[2];   // [H*F,O]
    const float* bias  = (const float*)d_in[3];   // [O]
    float* out = (float*)d_out;                   // [B,N,O]

    __nv_bfloat16 *nodes_h, *nodes_l, *nodesT_h, *nodesT_l, *WhT_h, *WhT_l;
    __nv_bfloat16 *WoT_h, *WoT_l, *xw_h, *xw_l, *att_h, *att_l, *ms_h, *ms_l;
    float* sc;
    cudaGetSymbolAddress((void**)&nodes_h,  g_nodes_h);
    cudaGetSymbolAddress((void**)&nodes_l,  g_nodes_l);
    cudaGetSymbolAddress((void**)&nodesT_h, g_nodesT_h);
    cudaGetSymbolAddress((void**)&nodesT_l, g_nodesT_l);
    cudaGetSymbolAddress((void**)&WhT_h,    g_WhT_h);
    cudaGetSymbolAddress((void**)&WhT_l,    g_WhT_l);
    cudaGetSymbolAddress((void**)&WoT_h,    g_WoT_h);
    cudaGetSymbolAddress((void**)&WoT_l,    g_WoT_l);
    cudaGetSymbolAddress((void**)&xw_h,     g_xw_h);
    cudaGetSymbolAddress((void**)&xw_l,     g_xw_l);
    cudaGetSymbolAddress((void**)&sc,       g_sc);
    cudaGetSymbolAddress((void**)&att_h,    g_att_h);
    cudaGetSymbolAddress((void**)&att_l,    g_att_l);
    cudaGetSymbolAddress((void**)&ms_h,     g_ms_h);
    cudaGetSymbolAddress((void**)&ms_l,     g_ms_l);

    constexpr int SMEM_BIG   = (256 + 128) * ROWB * NSTAGE;   // 122880
    constexpr int SMEM_SMALL = (128 + 128) * ROWB * NSTAGE;   //  81920
    cudaFuncSetAttribute(tc_gemm<256,0>, cudaFuncAttributeMaxDynamicSharedMemorySize, SMEM_BIG);
    cudaFuncSetAttribute(tc_gemm<256,2>, cudaFuncAttributeMaxDynamicSharedMemorySize, SMEM_BIG);
    cudaFuncSetAttribute(tc_gemm<128,1>, cudaFuncAttributeMaxDynamicSharedMemorySize, SMEM_SMALL);

    // ---- operand conversions (launches 1..3) --------------------------------
    split_nodes<<<dim3(Nn*Ff/256, Bsz), 256>>>(nodes, nodes_h, nodes_l, nodesT_h, nodesT_l);
    split_trans<<<dim3((Ff*Ff + 255) / 256, Hh), 256>>>(Wh, WhT_h, WhT_l, Ff, Ff);
    split_trans<<<dim3((Hh*Ff*Oo + 255) / 256, 1), 256>>>(Wo, WoT_h, WoT_l, Hh*Ff, Oo);

    const float norm = 0.0625f;   // 1/sqrt(256), folded into xw

    // 4) xw = norm * nodes @ Wh^T(pre-transposed)   (split output)  [launch 4]
    tc_gemm<256,2><<<dim3(Ff/128, Nn/256, Bsz*Hh), 512, SMEM_BIG>>>(
        nodes_h, nodes_l, WhT_h, WhT_l,
        nullptr, xw_h, xw_l, nullptr,
        Ff, Ff, Ff, Ff,
        (long long)Nn*Ff, 0,
        0, (long long)Ff*Ff,
        (long long)Hh*Nn*Ff, (long long)Nn*Ff,
        Hh, norm);

    // dummy no-op-scale launch so scores GEMM lands at ncu slot (-s 5 -> 6th)
    // (actually launch order is already: 3 conversions + gemm1 = 4, scores = 5th;
    //  -s 5 profiles the 6th launch = softmax. Insert scores as 6th by putting
    //  softmax prep after. Simpler: keep order; scores is launch 5,
    //  msgs GEMM is launch 7. Profile will catch softmax or msgs — both useful.)

    // 5) scores = xw @ nodes^T   (fp32 output)      [launch 5]
    tc_gemm<256,0><<<dim3(Nn/128, Nn/256, Bsz*Hh), 512, SMEM_BIG>>>(
        xw_h, xw_l, nodes_h, nodes_l,
        sc, nullptr, nullptr, nullptr,
        Ff, Ff, Ff, Nn,
        (long long)Hh*Nn*Ff, (long long)Nn*Ff,
        (long long)Nn*Ff, 0,
        (long long)Hh*Nn*Nn, (long long)Nn*Nn,
        Hh, 1.0f);

    // 6) softmax -> att hi/lo                        [launch 6]
    softmax2048s<<<Bsz*Hh*Nn, 256>>>(sc, att_h, att_l);

    // 7) msgs = att @ nodes  (split output, concat layout [B,N,H*F])
    tc_gemm<256,2><<<dim3(Ff/128, Nn/256, Bsz*Hh), 512, SMEM_BIG>>>(
        att_h, att_l, nodesT_h, nodesT_l,
        nullptr, ms_h, ms_l, nullptr,
        Nn, Nn, Nn, Hh*Ff,
        (long long)Hh*Nn*Nn, (long long)Nn*Nn,
        (long long)Ff*Nn, 0,
        (long long)Nn*Hh*Ff, (long long)Ff,
        Hh, 1.0f);

    // 8) out = msgs @ Wout + bias  (128-tile: 128 CTAs vs 64 at 256-tile)
    tc_gemm<128,1><<<dim3(Oo/128, Nn/128, Bsz), 256, SMEM_SMALL>>>(
        ms_h, ms_l, WoT_h, WoT_l,
        out, nullptr, nullptr, bias,
        Hh*Ff, Hh*Ff, Hh*Ff, Oo,
        (long long)Nn*Hh*Ff, 0,
        0, 0,
        (long long)Nn*Oo, 0,
        1, 1.0f);
}

// round 8
// speedup vs baseline: 3.2490x; 1.3749x over previous
#include <cuda_runtime.h>
#include <cuda_fp16.h>
#include <cstdint>

#define Bsz 4
#define Nn  2048
#define Ff  256
#define Hh  8
#define Oo  256

// ------------------------- device scratch (no allocs) -----------------------
__device__ __align__(256) __half g_nodes_h[(size_t)Bsz*Nn*Ff];
__device__ __align__(256) __half g_nodes_l[(size_t)Bsz*Nn*Ff];
__device__ __align__(256) __half g_nodesT_h[(size_t)Bsz*Ff*Nn];
__device__ __align__(256) __half g_WhT_h[(size_t)Hh*Ff*Ff];
__device__ __align__(256) __half g_WhT_l[(size_t)Hh*Ff*Ff];
__device__ __align__(256) __half g_WoT_h[(size_t)Oo*Hh*Ff];
__device__ __align__(256) __half g_xw_h[(size_t)Bsz*Hh*Nn*Ff];
__device__ __align__(256) __half g_xw_l[(size_t)Bsz*Hh*Nn*Ff];
__device__ __align__(256) float  g_sc  [(size_t)Bsz*Hh*Nn*Nn];
__device__ __align__(256) __half g_att_h[(size_t)Bsz*Hh*Nn*Nn];
__device__ __align__(256) __half g_att_l[(size_t)Bsz*Hh*Nn*Nn];
__device__ __align__(256) __half g_ms_h[(size_t)Bsz*Nn*Hh*Ff];
__device__ __align__(256) __half g_ms_l[(size_t)Bsz*Nn*Hh*Ff];

// ------------------------------ PTX helpers ---------------------------------
__device__ __forceinline__ uint32_t smem_u32(const void* p) {
    uint32_t a;
    asm("{ .reg .u64 t; cvta.to.shared.u64 t, %1; cvt.u32.u64 %0, t; }" : "=r"(a) : "l"(p));
    return a;
}
#define CP_ASYNC16(dst, src) \
    asm volatile("cp.async.cg.shared.global [%0], [%1], 16;" :: "r"(dst), "l"(src))
#define CP_COMMIT() asm volatile("cp.async.commit_group;" ::: "memory")
#define CP_WAIT2()  asm volatile("cp.async.wait_group 2;" ::: "memory")

__device__ __forceinline__ void ldsm_x4(uint32_t& r0, uint32_t& r1, uint32_t& r2,
                                        uint32_t& r3, uint32_t addr) {
    asm volatile("ldmatrix.sync.aligned.m8n8.x4.shared.b16 {%0,%1,%2,%3}, [%4];"
                 : "=r"(r0), "=r"(r1), "=r"(r2), "=r"(r3) : "r"(addr));
}
__device__ __forceinline__ void mma_f16(float* d, const uint32_t* a, const uint32_t* b) {
    asm volatile(
        "mma.sync.aligned.m16n8k16.row.col.f32.f16.f16.f32 "
        "{%0,%1,%2,%3}, {%4,%5,%6,%7}, {%8,%9}, {%0,%1,%2,%3};"
        : "+f"(d[0]), "+f"(d[1]), "+f"(d[2]), "+f"(d[3])
        : "r"(a[0]), "r"(a[1]), "r"(a[2]), "r"(a[3]), "r"(b[0]), "r"(b[1]));
}

// --------------------------- smem layout constants ---------------------------
// Row pitch 80B (64B data + 16B pad): 80/16=5, gcd(5,8)=1 -> conflict-free
// ldmatrix 8-row phases.
#define ROWB      80
#define NSTAGE    4

// ----------------------------- tile load (cp.async) --------------------------
template <int TM>
__device__ __forceinline__ void load_chunk(
    uint32_t sb,
    const __half* __restrict__ A, const __half* __restrict__ B,
    int m0, int n0, int k0, int lda, int ldb, int tid)
{
#pragma unroll
    for (int q = 0; q < 4; q++) {                       // A: TM rows x 4 x 16B
        int u = q * TM + tid;
        int r = u >> 2, c = u & 3;
        const char* src = (const char*)(A + (size_t)(m0 + r) * lda + k0 + c * 8);
        CP_ASYNC16(sb + r * ROWB + c * 16, src);
    }
#pragma unroll
    for (int q = 0; q < 512 / TM; q++) {                // B: 128 rows x 4 x 16B
        int u = q * TM + tid;
        int r = u >> 2, c = u & 3;
        const char* src = (const char*)(B + (size_t)(n0 + r) * ldb + k0 + c * 8);
        CP_ASYNC16(sb + TM * ROWB + r * ROWB + c * 16, src);
    }
    CP_COMMIT();
}

// --------------------------------- GEMM --------------------------------------
// C[M,N] = alpha * A @ B^T, fp32 emulation via NPASS fp16 passes:
//   pass0 = Ah@Bh, pass1 = Al@Bh, pass2 = Ah@Bl (if NPASS==3)
// CTA tile TM x 128, TM threads, warp tile 64x64 (warps (TM/64) x 2).
// OUTMODE: 0=f32, 1=f32+bias, 2=split hi/lo fp16.
template <int TM, int NPASS, int OUTMODE>
__global__ __launch_bounds__(TM, 1) void tc_gemm(
    const __half* __restrict__ Ah, const __half* __restrict__ Al,
    const __half* __restrict__ Bh, const __half* __restrict__ Bl,
    float* __restrict__ C, __half* __restrict__ Ch, __half* __restrict__ Cl,
    const float* __restrict__ bias,
    int K, int lda, int ldb, int ldc,
    long long sA1, long long sA2, long long sB1, long long sB2,
    long long sC1, long long sC2, int Z2, float alpha)
{
    constexpr int WM = TM / 64;                  // warp rows
    constexpr int STAGE_SZ = (TM + 128) * ROWB;

    extern __shared__ char smem[];
    const uint32_t sbase = smem_u32(smem);
    const int tid = threadIdx.x, wid = tid >> 5, lane = tid & 31;
    const int warp_m = wid & (WM - 1), warp_n = wid / WM;

    const int z = blockIdx.z, z1 = z / Z2, z2 = z % Z2;
    Ah += (size_t)z1 * sA1 + (size_t)z2 * sA2;
    Al += (size_t)z1 * sA1 + (size_t)z2 * sA2;
    Bh += (size_t)z1 * sB1 + (size_t)z2 * sB2;
    Bl += (size_t)z1 * sB1 + (size_t)z2 * sB2;
    const size_t coff = (size_t)z1 * sC1 + (size_t)z2 * sC2;

    const int n0 = blockIdx.x * 128;
    const int m0 = blockIdx.y * TM;

    const int nk  = K >> 5;              // 32-wide chunks per pass
    const int nch = NPASS * nk;

    float acc[32][4];
#pragma unroll
    for (int i = 0; i < 32; i++)
#pragma unroll
        for (int j = 0; j < 4; j++) acc[i][j] = 0.f;

    // A x4: rows (lane&15), k-half (lane>>4)
    const uint32_t a_lane = (uint32_t)((lane & 15) * ROWB + (lane >> 4) * 16);
    // B x4: 16 n-rows (2 n8 tiles): row = (lane>>4)*8 + (lane&7), k-half (lane>>3)&1
    const uint32_t b_lane = (uint32_t)((((lane >> 4) << 3) + (lane & 7)) * ROWB +
                                       ((lane >> 3) & 1) * 16);

    // prologue
#pragma unroll
    for (int c = 0; c < NSTAGE - 1; c++) {
        int p = c / nk, kc = c - p * nk;
        const __half* Ap = (p == 1) ? Al : Ah;
        const __half* Bp = (p == 2) ? Bl : Bh;
        load_chunk<TM>(sbase + (c & (NSTAGE - 1)) * STAGE_SZ, Ap, Bp,
                       m0, n0, kc << 5, lda, ldb, tid);
    }

    for (int c = 0; c < nch; c++) {
        CP_WAIT2();
        __syncthreads();

        const uint32_t sb = sbase + (c & (NSTAGE - 1)) * STAGE_SZ;
        const uint32_t abase = sb + (uint32_t)(warp_m * 64 * ROWB) + a_lane;
        const uint32_t bbase = sb + (uint32_t)(TM * ROWB) +
                               (uint32_t)(warp_n * 64 * ROWB) + b_lane;

#pragma unroll
        for (int ks = 0; ks < 2; ks++) {        // two k16 steps per 32-chunk
            uint32_t af[4][4], bfr[16];
#pragma unroll
            for (int mi = 0; mi < 4; mi++)
                ldsm_x4(af[mi][0], af[mi][1], af[mi][2], af[mi][3],
                        abase + mi * 16 * ROWB + ks * 32);
#pragma unroll
            for (int g = 0; g < 4; g++)          // 4 x (16 n-rows)
                ldsm_x4(bfr[g * 4 + 0], bfr[g * 4 + 1], bfr[g * 4 + 2], bfr[g * 4 + 3],
                        bbase + g * 16 * ROWB + ks * 32);
#pragma unroll
            for (int mi = 0; mi < 4; mi++)
#pragma unroll
                for (int ni = 0; ni < 8; ni++)
                    mma_f16(acc[mi * 8 + ni], af[mi], &bfr[ni * 2]);
        }

        if (c + NSTAGE - 1 < nch) {
            int cn = c + NSTAGE - 1;
            int p = cn / nk, kc = cn - p * nk;
            const __half* Ap = (p == 1) ? Al : Ah;
            const __half* Bp = (p == 2) ? Bl : Bh;
            load_chunk<TM>(sbase + (cn & (NSTAGE - 1)) * STAGE_SZ, Ap, Bp,
                           m0, n0, kc << 5, lda, ldb, tid);
        } else {
            CP_COMMIT();          // keep wait_group accounting exact at tail
        }
    }

    // ---------------- epilogue: registers -> GMEM ----------------------------
    const int r0 = m0 + warp_m * 64 + (lane >> 2);
    const int c0 = n0 + warp_n * 64 + (lane & 3) * 2;
#pragma unroll
    for (int mi = 0; mi < 4; mi++) {
#pragma unroll
        for (int ni = 0; ni < 8; ni++) {
            float* d = acc[mi * 8 + ni];
            const int gr = r0 + mi * 16;
            const int gc = c0 + ni * 8;
#pragma unroll
            for (int h = 0; h < 2; h++) {       // rows gr, gr+8
                float vx = d[h * 2 + 0] * alpha;
                float vy = d[h * 2 + 1] * alpha;
                const size_t off = coff + (size_t)(gr + h * 8) * ldc + gc;
                if (OUTMODE == 2) {
                    __half hx = __float2half_rn(vx);
                    __half hy = __float2half_rn(vy);
                    __half lx = __float2half_rn(vx - __half2float(hx));
                    __half ly = __float2half_rn(vy - __half2float(hy));
                    *reinterpret_cast<__half2*>(Ch + off) = __halves2half2(hx, hy);
                    *reinterpret_cast<__half2*>(Cl + off) = __halves2half2(lx, ly);
                } else {
                    if (OUTMODE == 1) { vx += bias[gc]; vy += bias[gc + 1]; }
                    float2 o; o.x = vx; o.y = vy;
                    *reinterpret_cast<float2*>(C + off) = o;
                }
            }
        }
    }
}

// ------------------------------ helper kernels --------------------------------
// nodes [B][N][F] -> row-major hi/lo AND transposed-hi [B][F][N] in one read
__global__ __launch_bounds__(256) void split_nodes(
    const float* __restrict__ in,
    __half* __restrict__ oh, __half* __restrict__ ol,
    __half* __restrict__ th)
{
    const size_t base = (size_t)blockIdx.y * (size_t)Nn * Ff;
    int i = blockIdx.x * 256 + threadIdx.x;
    int r = i >> 8, c = i & 255;            // F = 256
    float v = in[base + i];
    __half h = __float2half_rn(v);
    __half l = __float2half_rn(v - __half2float(h));
    oh[base + i] = h;
    ol[base + i] = l;
    th[base + (size_t)c * Nn + r] = h;
}

// in: [Z][R][C] fp32  ->  out hi(/lo): [Z][C][R] fp16
template <bool LO>
__global__ __launch_bounds__(256) void split_trans(
    const float* __restrict__ in, __half* __restrict__ oh,
    __half* __restrict__ ol, int R, int C)
{
    const size_t base = (size_t)blockIdx.y * (size_t)R * C;
    int i = blockIdx.x * 256 + threadIdx.x;
    if (i < R * C) {
        int r = i / C, c = i - r * C;
        float v = in[base + i];
        size_t o = base + (size_t)c * R + r;
        __half h = __float2half_rn(v);
        oh[o] = h;
        if (LO) ol[o] = __float2half_rn(v - __half2float(h));
    }
}

__global__ void nop_kernel() {}

// softmax over rows of 2048 fp32, emits att hi/lo fp16
__global__ __launch_bounds__(256) void softmax2048s(
    const float* __restrict__ s, __half* __restrict__ ah,
    __half* __restrict__ al)
{
    const size_t base = (size_t)blockIdx.x * 2048;
    const int tid = threadIdx.x;
    __shared__ float red[256];

    float v[8];
    float m = -1e30f;
#pragma unroll
    for (int i = 0; i < 8; i++) {
        v[i] = s[base + tid + i * 256];
        m = fmaxf(m, v[i]);
    }
    red[tid] = m;
    __syncthreads();
#pragma unroll
    for (int off = 128; off > 0; off >>= 1) {
        if (tid < off) red[tid] = fmaxf(red[tid], red[tid + off]);
        __syncthreads();
    }
    m = red[0];
    __syncthreads();

    float sum = 0.f;
#pragma unroll
    for (int i = 0; i < 8; i++) {
        v[i] = __expf(v[i] - m);
        sum += v[i];
    }
    red[tid] = sum;
    __syncthreads();
#pragma unroll
    for (int off = 128; off > 0; off >>= 1) {
        if (tid < off) red[tid] += red[tid + off];
        __syncthreads();
    }
    const float inv = 1.0f / red[0];
#pragma unroll
    for (int i = 0; i < 8; i++) {
        float p = v[i] * inv;
        __half h = __float2half_rn(p);
        ah[base + tid + i * 256] = h;
        al[base + tid + i * 256] = __float2half_rn(p - __half2float(h));
    }
}

// ---------------------------------- launch ------------------------------------
extern "C" void kernel_launch(void* const* d_in, const int* in_sizes, int n_in,
                              void* d_out, int out_size)
{
    const float* nodes = (const float*)d_in[0];   // [B,N,F]
    const float* Wh    = (const float*)d_in[1];   // [H,F,F]
    const float* Wo    = (const float*)d_in[2];   // [H*F,O]
    const float* bias  = (const float*)d_in[3];   // [O]
    float* out = (float*)d_out;                   // [B,N,O]

    __half *nodes_h, *nodes_l, *nodesT_h, *WhT_h, *WhT_l;
    __half *WoT_h, *xw_h, *xw_l, *att_h, *att_l, *ms_h, *ms_l;
    float* sc;
    cudaGetSymbolAddress((void**)&nodes_h,  g_nodes_h);
    cudaGetSymbolAddress((void**)&nodes_l,  g_nodes_l);
    cudaGetSymbolAddress((void**)&nodesT_h, g_nodesT_h);
    cudaGetSymbolAddress((void**)&WhT_h,    g_WhT_h);
    cudaGetSymbolAddress((void**)&WhT_l,    g_WhT_l);
    cudaGetSymbolAddress((void**)&WoT_h,    g_WoT_h);
    cudaGetSymbolAddress((void**)&xw_h,     g_xw_h);
    cudaGetSymbolAddress((void**)&xw_l,     g_xw_l);
    cudaGetSymbolAddress((void**)&sc,       g_sc);
    cudaGetSymbolAddress((void**)&att_h,    g_att_h);
    cudaGetSymbolAddress((void**)&att_l,    g_att_l);
    cudaGetSymbolAddress((void**)&ms_h,     g_ms_h);
    cudaGetSymbolAddress((void**)&ms_l,     g_ms_l);

    constexpr int SMEM_BIG   = (256 + 128) * ROWB * NSTAGE;   // 122880
    constexpr int SMEM_SMALL = (128 + 128) * ROWB * NSTAGE;   //  81920
    cudaFuncSetAttribute(tc_gemm<256,3,2>, cudaFuncAttributeMaxDynamicSharedMemorySize, SMEM_BIG);
    cudaFuncSetAttribute(tc_gemm<256,2,0>, cudaFuncAttributeMaxDynamicSharedMemorySize, SMEM_BIG);
    cudaFuncSetAttribute(tc_gemm<256,2,2>, cudaFuncAttributeMaxDynamicSharedMemorySize, SMEM_BIG);
    cudaFuncSetAttribute(tc_gemm<128,2,1>, cudaFuncAttributeMaxDynamicSharedMemorySize, SMEM_SMALL);

    // ---- operand conversions (launches 1..3) --------------------------------
    split_nodes<<<dim3(Nn*Ff/256, Bsz), 256>>>(nodes, nodes_h, nodes_l, nodesT_h);
    split_trans<true><<<dim3((Ff*Ff + 255) / 256, Hh), 256>>>(Wh, WhT_h, WhT_l, Ff, Ff);
    split_trans<false><<<dim3((Hh*Ff*Oo + 255) / 256, 1), 256>>>(Wo, WoT_h, nullptr, Hh*Ff, Oo);

    const float norm = 0.0625f;   // 1/sqrt(256), folded into xw

    // 4) xw = norm * nodes @ Wh^T   (3-pass, split output)
    tc_gemm<256,3,2><<<dim3(Ff/128, Nn/256, Bsz*Hh), 256, SMEM_BIG>>>(
        nodes_h, nodes_l, WhT_h, WhT_l,
        nullptr, xw_h, xw_l, nullptr,
        Ff, Ff, Ff, Ff,
        (long long)Nn*Ff, 0,
        0, (long long)Ff*Ff,
        (long long)Hh*Nn*Ff, (long long)Nn*Ff,
        Hh, norm);

    // 5) nop so scores GEMM lands in the ncu -s 5 -c 1 slot (6th launch)
    nop_kernel<<<1, 32>>>();

    // 6) scores = xw @ nodes^T  (2-pass, fp32 output)
    tc_gemm<256,2,0><<<dim3(Nn/128, Nn/256, Bsz*Hh), 256, SMEM_BIG>>>(
        xw_h, xw_l, nodes_h, nodes_h,
        sc, nullptr, nullptr, nullptr,
        Ff, Ff, Ff, Nn,
        (long long)Hh*Nn*Ff, (long long)Nn*Ff,
        (long long)Nn*Ff, 0,
        (long long)Hh*Nn*Nn, (long long)Nn*Nn,
        Hh, 1.0f);

    // 7) softmax -> att hi/lo
    softmax2048s<<<Bsz*Hh*Nn, 256>>>(sc, att_h, att_l);

    // 8) msgs = att @ nodesT^T  (2-pass, split output, concat layout [B,N,H*F])
    tc_gemm<256,2,2><<<dim3(Ff/128, Nn/256, Bsz*Hh), 256, SMEM_BIG>>>(
        att_h, att_l, nodesT_h, nodesT_h,
        nullptr, ms_h, ms_l, nullptr,
        Nn, Nn, Nn, Hh*Ff,
        (long long)Hh*Nn*Nn, (long long)Nn*Nn,
        (long long)Ff*Nn, 0,
        (long long)Nn*Hh*Ff, (long long)Ff,
        Hh, 1.0f);

    // 9) out = msgs @ Wout + bias  (2-pass, 128-tile: 128 CTAs)
    tc_gemm<128,2,1><<<dim3(Oo/128, Nn/128, Bsz), 128, SMEM_SMALL>>>(
        ms_h, ms_l, WoT_h, WoT_h,
        out, nullptr, nullptr, bias,
        Hh*Ff, Hh*Ff, Hh*Ff, Oo,
        (long long)Nn*Hh*Ff, 0,
        0, 0,
        (long long)Nn*Oo, 0,
        1, 1.0f);
}

// round 9
// speedup vs baseline: 3.3445x; 1.0294x over previous
#include <cuda_runtime.h>
#include <cuda_fp16.h>
#include <cstdint>

#define Bsz 4
#define Nn  2048
#define Ff  256
#define Hh  8
#define Oo  256

// ------------------------- device scratch (no allocs) -----------------------
__device__ __align__(256) __half g_nodes_h[(size_t)Bsz*Nn*Ff];
__device__ __align__(256) __half g_nodes_l[(size_t)Bsz*Nn*Ff];
__device__ __align__(256) __half g_nodesT_h[(size_t)Bsz*Ff*Nn];
__device__ __align__(256) __half g_WhT_h[(size_t)Hh*Ff*Ff];
__device__ __align__(256) __half g_WhT_l[(size_t)Hh*Ff*Ff];
__device__ __align__(256) __half g_WoT_h[(size_t)Oo*Hh*Ff];
__device__ __align__(256) __half g_xw_h[(size_t)Bsz*Hh*Nn*Ff];
__device__ __align__(256) __half g_xw_l[(size_t)Bsz*Hh*Nn*Ff];
__device__ __align__(256) float  g_sc  [(size_t)Bsz*Hh*Nn*Nn];
__device__ __align__(256) __half g_att_h[(size_t)Bsz*Hh*Nn*Nn];
__device__ __align__(256) __half g_att_l[(size_t)Bsz*Hh*Nn*Nn];
__device__ __align__(256) __half g_ms_h[(size_t)Bsz*Nn*Hh*Ff];
__device__ __align__(256) __half g_ms_l[(size_t)Bsz*Nn*Hh*Ff];

// ------------------------------ PTX helpers ---------------------------------
__device__ __forceinline__ uint32_t smem_u32(const void* p) {
    uint32_t a;
    asm("{ .reg .u64 t; cvta.to.shared.u64 t, %1; cvt.u32.u64 %0, t; }" : "=r"(a) : "l"(p));
    return a;
}
#define CP_ASYNC16(dst, src) \
    asm volatile("cp.async.cg.shared.global [%0], [%1], 16;" :: "r"(dst), "l"(src))
#define CP_COMMIT() asm volatile("cp.async.commit_group;" ::: "memory")
#define CP_WAIT1()  asm volatile("cp.async.wait_group 1;" ::: "memory")

__device__ __forceinline__ void ldsm_x4(uint32_t& r0, uint32_t& r1, uint32_t& r2,
                                        uint32_t& r3, uint32_t addr) {
    asm volatile("ldmatrix.sync.aligned.m8n8.x4.shared.b16 {%0,%1,%2,%3}, [%4];"
                 : "=r"(r0), "=r"(r1), "=r"(r2), "=r"(r3) : "r"(addr));
}
__device__ __forceinline__ void mma_f16(float* d, const uint32_t* a, const uint32_t* b) {
    asm volatile(
        "mma.sync.aligned.m16n8k16.row.col.f32.f16.f16.f32 "
        "{%0,%1,%2,%3}, {%4,%5,%6,%7}, {%8,%9}, {%0,%1,%2,%3};"
        : "+f"(d[0]), "+f"(d[1]), "+f"(d[2]), "+f"(d[3])
        : "r"(a[0]), "r"(a[1]), "r"(a[2]), "r"(a[3]), "r"(b[0]), "r"(b[1]));
}

// --------------------------- smem layout constants ---------------------------
// K-chunk 64 fp16 = 128B data/row; pitch 144B (9x16B, gcd(9,8)=1 -> the 8
// 16B-segments of any 8 consecutive rows land in 8 distinct 128B phases:
// conflict-free ldmatrix AND conflict-free cp.async stores.
#define ROWB      144
#define NSTAGE    3

__device__ __forceinline__ void ld_afrag(uint32_t* af, uint32_t abase, int ks) {
#pragma unroll
    for (int mi = 0; mi < 4; mi++)
        ldsm_x4(af[mi*4+0], af[mi*4+1], af[mi*4+2], af[mi*4+3],
                abase + mi * 16 * ROWB + ks * 32);
}

// ----------------------------- tile load (cp.async) --------------------------
template <int TM>
__device__ __forceinline__ void load_chunk(
    uint32_t sb,
    const __half* __restrict__ A, const __half* __restrict__ B,
    int m0, int n0, int k0, int lda, int ldb, int tid)
{
#pragma unroll
    for (int q = 0; q < 8; q++) {                       // A: TM rows x 8 x 16B
        int u = q * TM + tid;
        int r = u >> 3, c = u & 7;
        const char* src = (const char*)(A + (size_t)(m0 + r) * lda + k0 + c * 8);
        CP_ASYNC16(sb + r * ROWB + c * 16, src);
    }
#pragma unroll
    for (int q = 0; q < 1024 / TM; q++) {               // B: 128 rows x 8 x 16B
        int u = q * TM + tid;
        int r = u >> 3, c = u & 7;
        const char* src = (const char*)(B + (size_t)(n0 + r) * ldb + k0 + c * 8);
        CP_ASYNC16(sb + TM * ROWB + r * ROWB + c * 16, src);
    }
    CP_COMMIT();
}

// --------------------------------- GEMM --------------------------------------
// C[M,N] = alpha * A @ B^T, fp32 emulation via NPASS fp16 passes:
//   pass0 = Ah@Bh, pass1 = Al@Bh, pass2 = Ah@Bl (if NPASS==3)
// CTA tile TM x 128, TM threads, warp tile 64x64 (warps (TM/64) x 2).
// K-chunk 64, 3-stage cp.async pipeline, loads issued BEFORE the MMA block,
// double-buffered ldmatrix fragments (B per 16-row group, A per k16 step).
// OUTMODE: 0=f32, 1=f32+bias, 2=split hi/lo fp16.
template <int TM, int NPASS, int OUTMODE>
__global__ __launch_bounds__(TM, 1) void tc_gemm(
    const __half* __restrict__ Ah, const __half* __restrict__ Al,
    const __half* __restrict__ Bh, const __half* __restrict__ Bl,
    float* __restrict__ C, __half* __restrict__ Ch, __half* __restrict__ Cl,
    const float* __restrict__ bias,
    int K, int lda, int ldb, int ldc,
    long long sA1, long long sA2, long long sB1, long long sB2,
    long long sC1, long long sC2, int Z2, float alpha)
{
    constexpr int WM = TM / 64;                  // warp rows
    constexpr int STAGE_SZ = (TM + 128) * ROWB;

    extern __shared__ char smem[];
    const uint32_t sbase = smem_u32(smem);
    const int tid = threadIdx.x, wid = tid >> 5, lane = tid & 31;
    const int warp_m = wid & (WM - 1), warp_n = wid / WM;

    const int z = blockIdx.z, z1 = z / Z2, z2 = z % Z2;
    Ah += (size_t)z1 * sA1 + (size_t)z2 * sA2;
    Al += (size_t)z1 * sA1 + (size_t)z2 * sA2;
    Bh += (size_t)z1 * sB1 + (size_t)z2 * sB2;
    Bl += (size_t)z1 * sB1 + (size_t)z2 * sB2;
    const size_t coff = (size_t)z1 * sC1 + (size_t)z2 * sC2;

    const int n0 = blockIdx.x * 128;
    const int m0 = blockIdx.y * TM;

    const int nk  = K >> 6;              // 64-wide chunks per pass
    const int nch = NPASS * nk;

    float acc[32][4];
#pragma unroll
    for (int i = 0; i < 32; i++)
#pragma unroll
        for (int j = 0; j < 4; j++) acc[i][j] = 0.f;

    // A x4: rows (lane&15), k-half (lane>>4)
    const uint32_t a_lane = (uint32_t)((lane & 15) * ROWB + (lane >> 4) * 16);
    // B x4: rows (lane>>4)*8 + (lane&7), k-half (lane>>3)&1
    const uint32_t b_lane = (uint32_t)((((lane >> 4) << 3) + (lane & 7)) * ROWB +
                                       ((lane >> 3) & 1) * 16);

    // prologue: chunks 0,1 -> stages 0,1
#pragma unroll
    for (int c = 0; c < NSTAGE - 1; c++) {
        int p = c / nk, kc = c - p * nk;
        const __half* Ap = (p == 1) ? Al : Ah;
        const __half* Bp = (p == 2) ? Bl : Bh;
        load_chunk<TM>(sbase + c * STAGE_SZ, Ap, Bp,
                       m0, n0, kc << 6, lda, ldb, tid);
    }

    int st = 0, stl = NSTAGE - 1;
    for (int c = 0; c < nch; c++) {
        CP_WAIT1();
        __syncthreads();

        // issue next chunk's loads FIRST so DMA overlaps the MMA block below
        if (c + 2 < nch) {
            int cn = c + 2;
            int p = cn / nk, kc = cn - p * nk;
            const __half* Ap = (p == 1) ? Al : Ah;
            const __half* Bp = (p == 2) ? Bl : Bh;
            load_chunk<TM>(sbase + stl * STAGE_SZ, Ap, Bp,
                           m0, n0, kc << 6, lda, ldb, tid);
        } else {
            CP_COMMIT();
        }

        const uint32_t sb = sbase + st * STAGE_SZ;
        const uint32_t abase = sb + (uint32_t)(warp_m * 64 * ROWB) + a_lane;
        const uint32_t bbase = sb + (uint32_t)(TM * ROWB) +
                               (uint32_t)(warp_n * 64 * ROWB) + b_lane;

        uint32_t af[2][16], bf[2][4];
        ld_afrag(af[0], abase, 0);

#pragma unroll
        for (int ks = 0; ks < 4; ks++) {
            const int cur = ks & 1;
            ldsm_x4(bf[0][0], bf[0][1], bf[0][2], bf[0][3], bbase + ks * 32);
#pragma unroll
            for (int g = 0; g < 4; g++) {
                const int cb = g & 1;
                if (g < 3)
                    ldsm_x4(bf[cb ^ 1][0], bf[cb ^ 1][1], bf[cb ^ 1][2], bf[cb ^ 1][3],
                            bbase + (g + 1) * 16 * ROWB + ks * 32);
                else if (ks < 3)
                    ld_afrag(af[cur ^ 1], abase, ks + 1);
#pragma unroll
                for (int mi = 0; mi < 4; mi++) {
                    mma_f16(acc[mi * 8 + 2 * g],     &af[cur][mi * 4], &bf[cb][0]);
                    mma_f16(acc[mi * 8 + 2 * g + 1], &af[cur][mi * 4], &bf[cb][2]);
                }
            }
        }

        if (++st == NSTAGE) st = 0;
        if (++stl == NSTAGE) stl = 0;
    }

    // ---------------- epilogue: registers -> GMEM ----------------------------
    const int r0 = m0 + warp_m * 64 + (lane >> 2);
    const int c0 = n0 + warp_n * 64 + (lane & 3) * 2;
#pragma unroll
    for (int mi = 0; mi < 4; mi++) {
#pragma unroll
        for (int ni = 0; ni < 8; ni++) {
            float* d = acc[mi * 8 + ni];
            const int gr = r0 + mi * 16;
            const int gc = c0 + ni * 8;
#pragma unroll
            for (int h = 0; h < 2; h++) {       // rows gr, gr+8
                float vx = d[h * 2 + 0] * alpha;
                float vy = d[h * 2 + 1] * alpha;
                const size_t off = coff + (size_t)(gr + h * 8) * ldc + gc;
                if (OUTMODE == 2) {
                    __half hx = __float2half_rn(vx);
                    __half hy = __float2half_rn(vy);
                    __half lx = __float2half_rn(vx - __half2float(hx));
                    __half ly = __float2half_rn(vy - __half2float(hy));
                    *reinterpret_cast<__half2*>(Ch + off) = __halves2half2(hx, hy);
                    *reinterpret_cast<__half2*>(Cl + off) = __halves2half2(lx, ly);
                } else {
                    if (OUTMODE == 1) { vx += bias[gc]; vy += bias[gc + 1]; }
                    float2 o; o.x = vx; o.y = vy;
                    *reinterpret_cast<float2*>(C + off) = o;
                }
            }
        }
    }
}

// ------------------------------ helper kernels --------------------------------
// nodes [B][N][F] -> row-major hi/lo AND transposed-hi [B][F][N] in one read
__global__ __launch_bounds__(256) void split_nodes(
    const float* __restrict__ in,
    __half* __restrict__ oh, __half* __restrict__ ol,
    __half* __restrict__ th)
{
    const size_t base = (size_t)blockIdx.y * (size_t)Nn * Ff;
    int i = blockIdx.x * 256 + threadIdx.x;
    int r = i >> 8, c = i & 255;            // F = 256
    float v = in[base + i];
    __half h = __float2half_rn(v);
    __half l = __float2half_rn(v - __half2float(h));
    oh[base + i] = h;
    ol[base + i] = l;
    th[base + (size_t)c * Nn + r] = h;
}

// in: [Z][R][C] fp32  ->  out hi(/lo): [Z][C][R] fp16
template <bool LO>
__global__ __launch_bounds__(256) void split_trans(
    const float* __restrict__ in, __half* __restrict__ oh,
    __half* __restrict__ ol, int R, int C)
{
    const size_t base = (size_t)blockIdx.y * (size_t)R * C;
    int i = blockIdx.x * 256 + threadIdx.x;
    if (i < R * C) {
        int r = i / C, c = i - r * C;
        float v = in[base + i];
        size_t o = base + (size_t)c * R + r;
        __half h = __float2half_rn(v);
        oh[o] = h;
        if (LO) ol[o] = __float2half_rn(v - __half2float(h));
    }
}

// softmax over rows of 2048 fp32, emits att hi/lo fp16
__global__ __launch_bounds__(256) void softmax2048s(
    const float* __restrict__ s, __half* __restrict__ ah,
    __half* __restrict__ al)
{
    const size_t base = (size_t)blockIdx.x * 2048;
    const int tid = threadIdx.x;
    __shared__ float red[256];

    float v[8];
    float m = -1e30f;
#pragma unroll
    for (int i = 0; i < 8; i++) {
        v[i] = s[base + tid + i * 256];
        m = fmaxf(m, v[i]);
    }
    red[tid] = m;
    __syncthreads();
#pragma unroll
    for (int off = 128; off > 0; off >>= 1) {
        if (tid < off) red[tid] = fmaxf(red[tid], red[tid + off]);
        __syncthreads();
    }
    m = red[0];
    __syncthreads();

    float sum = 0.f;
#pragma unroll
    for (int i = 0; i < 8; i++) {
        v[i] = __expf(v[i] - m);
        sum += v[i];
    }
    red[tid] = sum;
    __syncthreads();
#pragma unroll
    for (int off = 128; off > 0; off >>= 1) {
        if (tid < off) red[tid] += red[tid + off];
        __syncthreads();
    }
    const float inv = 1.0f / red[0];
#pragma unroll
    for (int i = 0; i < 8; i++) {
        float p = v[i] * inv;
        __half h = __float2half_rn(p);
        ah[base + tid + i * 256] = h;
        al[base + tid + i * 256] = __float2half_rn(p - __half2float(h));
    }
}

// ---------------------------------- launch ------------------------------------
extern "C" void kernel_launch(void* const* d_in, const int* in_sizes, int n_in,
                              void* d_out, int out_size)
{
    const float* nodes = (const float*)d_in[0];   // [B,N,F]
    const float* Wh    = (const float*)d_in[1];   // [H,F,F]
    const float* Wo    = (const float*)d_in[2];   // [H*F,O]
    const float* bias  = (const float*)d_in[3];   // [O]
    float* out = (float*)d_out;                   // [B,N,O]

    __half *nodes_h, *nodes_l, *nodesT_h, *WhT_h, *WhT_l;
    __half *WoT_h, *xw_h, *xw_l, *att_h, *att_l, *ms_h, *ms_l;
    float* sc;
    cudaGetSymbolAddress((void**)&nodes_h,  g_nodes_h);
    cudaGetSymbolAddress((void**)&nodes_l,  g_nodes_l);
    cudaGetSymbolAddress((void**)&nodesT_h, g_nodesT_h);
    cudaGetSymbolAddress((void**)&WhT_h,    g_WhT_h);
    cudaGetSymbolAddress((void**)&WhT_l,    g_WhT_l);
    cudaGetSymbolAddress((void**)&WoT_h,    g_WoT_h);
    cudaGetSymbolAddress((void**)&xw_h,     g_xw_h);
    cudaGetSymbolAddress((void**)&xw_l,     g_xw_l);
    cudaGetSymbolAddress((void**)&sc,       g_sc);
    cudaGetSymbolAddress((void**)&att_h,    g_att_h);
    cudaGetSymbolAddress((void**)&att_l,    g_att_l);
    cudaGetSymbolAddress((void**)&ms_h,     g_ms_h);
    cudaGetSymbolAddress((void**)&ms_l,     g_ms_l);

    constexpr int SMEM_BIG   = (256 + 128) * ROWB * NSTAGE;   // 165888
    constexpr int SMEM_SMALL = (128 + 128) * ROWB * NSTAGE;   // 110592
    cudaFuncSetAttribute(tc_gemm<256,3,2>, cudaFuncAttributeMaxDynamicSharedMemorySize, SMEM_BIG);
    cudaFuncSetAttribute(tc_gemm<256,2,0>, cudaFuncAttributeMaxDynamicSharedMemorySize, SMEM_BIG);
    cudaFuncSetAttribute(tc_gemm<256,2,2>, cudaFuncAttributeMaxDynamicSharedMemorySize, SMEM_BIG);
    cudaFuncSetAttribute(tc_gemm<128,2,1>, cudaFuncAttributeMaxDynamicSharedMemorySize, SMEM_SMALL);

    // ---- operand conversions -------------------------------------------------
    split_nodes<<<dim3(Nn*Ff/256, Bsz), 256>>>(nodes, nodes_h, nodes_l, nodesT_h);
    split_trans<true><<<dim3((Ff*Ff + 255) / 256, Hh), 256>>>(Wh, WhT_h, WhT_l, Ff, Ff);
    split_trans<false><<<dim3((Hh*Ff*Oo + 255) / 256, 1), 256>>>(Wo, WoT_h, nullptr, Hh*Ff, Oo);

    const float norm = 0.0625f;   // 1/sqrt(256), folded into xw

    // 4) xw = norm * nodes @ Wh^T   (3-pass, split output)
    tc_gemm<256,3,2><<<dim3(Ff/128, Nn/256, Bsz*Hh), 256, SMEM_BIG>>>(
        nodes_h, nodes_l, WhT_h, WhT_l,
        nullptr, xw_h, xw_l, nullptr,
        Ff, Ff, Ff, Ff,
        (long long)Nn*Ff, 0,
        0, (long long)Ff*Ff,
        (long long)Hh*Nn*Ff, (long long)Nn*Ff,
        Hh, norm);

    // 5) scores = xw @ nodes^T  (2-pass, fp32 output)
    tc_gemm<256,2,0><<<dim3(Nn/128, Nn/256, Bsz*Hh), 256, SMEM_BIG>>>(
        xw_h, xw_l, nodes_h, nodes_h,
        sc, nullptr, nullptr, nullptr,
        Ff, Ff, Ff, Nn,
        (long long)Hh*Nn*Ff, (long long)Nn*Ff,
        (long long)Nn*Ff, 0,
        (long long)Hh*Nn*Nn, (long long)Nn*Nn,
        Hh, 1.0f);

    // 6) softmax -> att hi/lo
    softmax2048s<<<Bsz*Hh*Nn, 256>>>(sc, att_h, att_l);

    // 7) msgs = att @ nodesT^T  (2-pass, split output, concat layout [B,N,H*F])
    tc_gemm<256,2,2><<<dim3(Ff/128, Nn/256, Bsz*Hh), 256, SMEM_BIG>>>(
        att_h, att_l, nodesT_h, nodesT_h,
        nullptr, ms_h, ms_l, nullptr,
        Nn, Nn, Nn, Hh*Ff,
        (long long)Hh*Nn*Nn, (long long)Nn*Nn,
        (long long)Ff*Nn, 0,
        (long long)Nn*Hh*Ff, (long long)Ff,
        Hh, 1.0f);

    // 8) out = msgs @ Wout + bias  (2-pass, 128-tile: 128 CTAs)
    tc_gemm<128,2,1><<<dim3(Oo/128, Nn/128, Bsz), 128, SMEM_SMALL>>>(
        ms_h, ms_l, WoT_h, WoT_h,
        out, nullptr, nullptr, bias,
        Hh*Ff, Hh*Ff, Hh*Ff, Oo,
        (long long)Nn*Hh*Ff, 0,
        0, 0,
        (long long)Nn*Oo, 0,
        1, 1.0f);
}